// round 12
// baseline (speedup 1.0000x reference)
#include <cuda_runtime.h>
#include <stdint.h>

// Problem constants (fixed: IM_SIZE=(1080,1920), SCALE=(0.25,0.25), B=8, C=3)
#define H_IN 1080
#define W_IN 1920
#define OH   270
#define OW   480
#define BC   24
#define MAX_TAPS 20
#define WQ   (W_IN / 4)

// Scratch: vertical-resized intermediate [BC, OH, W_IN] (~49.8 MB)
__device__ float g_mid[(size_t)BC * OH * W_IN];

// ---------------------------------------------------------------------------
// Pass 1: vertical resample, G=5 output rows per block for L1 tap-row reuse.
// Adjacent oh windows overlap 12/16 rows; p-outer g-inner ordering makes the
// repeat loads L1 hits, cutting L2-delivered traffic ~2.5x.
// grid: (WQ/128, OH/5, BC), block: 128
// ---------------------------------------------------------------------------
#define G_OH 5

template <int TAPS>
__global__ void __launch_bounds__(128)
pass1_vert(const float* __restrict__ x,
           const float* __restrict__ w_h,
           const int* __restrict__ idx_h,
           int taps_rt)
{
    const int taps = (TAPS > 0) ? TAPS : taps_rt;
    __shared__ float sw[G_OH * MAX_TAPS];
    __shared__ int   srow[G_OH * MAX_TAPS];

    const int oh0 = blockIdx.y * G_OH;
    const int bc  = blockIdx.z;
    const int t   = threadIdx.x;

    for (int i = t; i < G_OH * taps; i += 128) {
        const int g = i / taps;
        const int p = i - g * taps;
        sw[i] = w_h[(oh0 + g) * taps + p];
        int r = idx_h[(oh0 + g) * taps + p];
        r = (r < 0) ? 0 : (r > H_IN - 1 ? H_IN - 1 : r);
        srow[i] = r;
    }
    __syncthreads();

    const int wq = blockIdx.x * 128 + t;
    if (wq >= WQ) return;

    const float4* xin = (const float4*)x + (size_t)bc * H_IN * WQ + wq;

    if (TAPS > 0) {
        float4 a0 = make_float4(0,0,0,0), a1 = a0, a2 = a0, a3 = a0, a4 = a0;
#pragma unroll
        for (int p = 0; p < TAPS; ++p) {
            // g-inner: the overlapping-row reload (g+1,p-4)==(g,p) already
            // happened 20 loads earlier -> L1 hit.
            float4 v;
            float  w;
            v = __ldg(xin + (size_t)srow[0 * TAPS + p] * WQ); w = sw[0 * TAPS + p];
            a0.x += w * v.x; a0.y += w * v.y; a0.z += w * v.z; a0.w += w * v.w;
            v = __ldg(xin + (size_t)srow[1 * TAPS + p] * WQ); w = sw[1 * TAPS + p];
            a1.x += w * v.x; a1.y += w * v.y; a1.z += w * v.z; a1.w += w * v.w;
            v = __ldg(xin + (size_t)srow[2 * TAPS + p] * WQ); w = sw[2 * TAPS + p];
            a2.x += w * v.x; a2.y += w * v.y; a2.z += w * v.z; a2.w += w * v.w;
            v = __ldg(xin + (size_t)srow[3 * TAPS + p] * WQ); w = sw[3 * TAPS + p];
            a3.x += w * v.x; a3.y += w * v.y; a3.z += w * v.z; a3.w += w * v.w;
            v = __ldg(xin + (size_t)srow[4 * TAPS + p] * WQ); w = sw[4 * TAPS + p];
            a4.x += w * v.x; a4.y += w * v.y; a4.z += w * v.z; a4.w += w * v.w;
        }
        float4* mid4 = (float4*)g_mid + ((size_t)bc * OH + oh0) * WQ + wq;
        mid4[0 * WQ] = a0;
        mid4[1 * WQ] = a1;
        mid4[2 * WQ] = a2;
        mid4[3 * WQ] = a3;
        mid4[4 * WQ] = a4;
    } else {
        // generic fallback (not expected)
        for (int g = 0; g < G_OH; ++g) {
            float4 acc = make_float4(0,0,0,0);
            for (int p = 0; p < taps; ++p) {
                const float  w = sw[g * taps + p];
                const float4 v = __ldg(xin + (size_t)srow[g * taps + p] * WQ);
                acc.x += w * v.x; acc.y += w * v.y; acc.z += w * v.z; acc.w += w * v.w;
            }
            ((float4*)g_mid)[((size_t)bc * OH + oh0 + g) * WQ + wq] = acc;
        }
    }
}

// ---------------------------------------------------------------------------
// Pass 2: horizontal resample. Taps are contiguous columns, so gather = 5
// aligned LDS.128 (no skew needed: float4 staging + float4 gather are both
// naturally conflict-free). Double-buffered, one __syncthreads per row,
// next-row prefetch hidden under the gather. Edge threads (mirrored, non-
// contiguous taps) take a scalar fallback.
// grid: (1, OH/R, BC), block: 480
// ---------------------------------------------------------------------------
#define R_ROWS2 9                        // 270 % 9 == 0
#define SROW_PAD4 488                    // 1952 floats: base4<=1916, +20 < 1952

template <int TAPS>
__global__ void __launch_bounds__(480)
pass2_horiz(const float* __restrict__ w_w,
            const int* __restrict__ idx_w,
            float* __restrict__ out,
            int taps_rt)
{
    const int taps = (TAPS > 0) ? TAPS : taps_rt;
    __shared__ float4 buf4[2][SROW_PAD4];

    const int t   = threadIdx.x;         // == ow (OW == 480)
    const int bc  = blockIdx.z;
    const int oh0 = blockIdx.y * R_ROWS2;

    // Registerized per-thread weights + clamped indices
    float wreg[(TAPS > 0) ? TAPS : MAX_TAPS];
    int   creg[(TAPS > 0) ? TAPS : MAX_TAPS];
#pragma unroll
    for (int p = 0; p < ((TAPS > 0) ? TAPS : MAX_TAPS); ++p) {
        if (TAPS == 0 && p >= taps) break;
        wreg[p] = w_w[t * taps + p];
        int c = idx_w[t * taps + p];
        c = (c < 0) ? 0 : (c > W_IN - 1 ? W_IN - 1 : c);
        creg[p] = c;
    }

    // Contiguity check (interior outputs: taps are consecutive columns)
    bool contig = true;
#pragma unroll
    for (int p = 1; p < ((TAPS > 0) ? TAPS : MAX_TAPS); ++p) {
        if (TAPS == 0 && p >= taps) break;
        contig = contig && (creg[p] == creg[0] + p);
    }
    const int start = creg[0];
    const int off   = start & 3;
    const int base4 = (start - off) >> 2;          // float4 index; gather spans 5 float4

    const float4* rows = (const float4*)g_mid + ((size_t)bc * OH + oh0) * WQ + t;

    float4 v = __ldg(rows);                         // prefetch row 0

#pragma unroll
    for (int r = 0; r < R_ROWS2; ++r) {
        float4* cur4 = buf4[r & 1];

        cur4[t] = v;                                // STS.128, conflict-free
        __syncthreads();

        if (r + 1 < R_ROWS2)
            v = __ldg(rows + (size_t)(r + 1) * WQ); // prefetch next row

        float o;
        if (contig && TAPS == 16) {
            // 5 aligned LDS.128 -> 20 floats, then static dot at offset `off`
            float fr[20];
#pragma unroll
            for (int j = 0; j < 5; ++j) {
                float4 q = cur4[base4 + j];
                fr[4 * j + 0] = q.x; fr[4 * j + 1] = q.y;
                fr[4 * j + 2] = q.z; fr[4 * j + 3] = q.w;
            }
            float a0 = 0.f, a1 = 0.f;
            switch (off) {
            case 0:
#pragma unroll
                for (int p = 0; p < 16; p += 2) { a0 += wreg[p] * fr[p + 0]; a1 += wreg[p + 1] * fr[p + 1]; }
                break;
            case 1:
#pragma unroll
                for (int p = 0; p < 16; p += 2) { a0 += wreg[p] * fr[p + 1]; a1 += wreg[p + 1] * fr[p + 2]; }
                break;
            case 2:
#pragma unroll
                for (int p = 0; p < 16; p += 2) { a0 += wreg[p] * fr[p + 2]; a1 += wreg[p + 1] * fr[p + 3]; }
                break;
            default:
#pragma unroll
                for (int p = 0; p < 16; p += 2) { a0 += wreg[p] * fr[p + 3]; a1 += wreg[p + 1] * fr[p + 4]; }
                break;
            }
            o = a0 + a1;
        } else {
            // scalar fallback (edge mirror threads / generic taps)
            const float* cur = (const float*)cur4;
            float a0 = 0.f, a1 = 0.f;
#pragma unroll
            for (int p = 0; p < ((TAPS > 0) ? TAPS : MAX_TAPS); p += 2) {
                if (TAPS == 0 && p >= taps) break;
                a0 += wreg[p] * cur[creg[p]];
                if (TAPS > 0 || p + 1 < taps)
                    a1 += wreg[p + 1] * cur[creg[p + 1]];
            }
            o = a0 + a1;
        }

        out[((size_t)bc * OH + oh0 + r) * OW + t] = o;
    }
}

// ---------------------------------------------------------------------------
// kernel_launch
// inputs: x(f32), w_h(f32), idx_h(i32), w_w(f32), idx_w(i32); output f32
// ---------------------------------------------------------------------------
extern "C" void kernel_launch(void* const* d_in, const int* in_sizes, int n_in,
                              void* d_out, int out_size)
{
    const float* x     = (const float*)d_in[0];
    const float* w_h   = (const float*)d_in[1];
    const int*   idx_h = (const int*)d_in[2];
    const float* w_w   = (const float*)d_in[3];
    const int*   idx_w = (const int*)d_in[4];
    float*       out   = (float*)d_out;

    int taps_h = in_sizes[1] / OH;
    int taps_w = in_sizes[3] / OW;
    if (taps_h > MAX_TAPS) taps_h = MAX_TAPS;
    if (taps_w > MAX_TAPS) taps_w = MAX_TAPS;

    {
        dim3 grid((WQ + 127) / 128, OH / G_OH, BC);  // (4, 54, 24)
        if (taps_h == 16)
            pass1_vert<16><<<grid, 128>>>(x, w_h, idx_h, taps_h);
        else
            pass1_vert<0><<<grid, 128>>>(x, w_h, idx_h, taps_h);
    }
    {
        dim3 grid(1, OH / R_ROWS2, BC);              // (1, 30, 24)
        if (taps_w == 16)
            pass2_horiz<16><<<grid, 480>>>(w_w, idx_w, out, taps_w);
        else
            pass2_horiz<0><<<grid, 480>>>(w_w, idx_w, out, taps_w);
    }
}

// round 13
// speedup vs baseline: 1.0281x; 1.0281x over previous
#include <cuda_runtime.h>
#include <stdint.h>

// Problem constants (fixed: IM_SIZE=(1080,1920), SCALE=(0.25,0.25), B=8, C=3)
#define H_IN 1080
#define W_IN 1920
#define OH   270
#define OW   480
#define BC   24
#define MAX_TAPS 20
#define WQ   (W_IN / 4)

// Scratch: vertical-resized intermediate [BC, OH, W_IN] (~49.8 MB)
__device__ float g_mid[(size_t)BC * OH * W_IN];

// ---------------------------------------------------------------------------
// Pass 1: vertical resample, G=5 output rows per block (DRAM-floor bound).
// grid: (WQ/128, OH/5, BC), block: 128
// ---------------------------------------------------------------------------
#define G_OH 5

template <int TAPS>
__global__ void __launch_bounds__(128)
pass1_vert(const float* __restrict__ x,
           const float* __restrict__ w_h,
           const int* __restrict__ idx_h,
           int taps_rt)
{
    const int taps = (TAPS > 0) ? TAPS : taps_rt;
    __shared__ float sw[G_OH * MAX_TAPS];
    __shared__ int   srow[G_OH * MAX_TAPS];

    const int oh0 = blockIdx.y * G_OH;
    const int bc  = blockIdx.z;
    const int t   = threadIdx.x;

    for (int i = t; i < G_OH * taps; i += 128) {
        const int g = i / taps;
        const int p = i - g * taps;
        sw[i] = w_h[(oh0 + g) * taps + p];
        int r = idx_h[(oh0 + g) * taps + p];
        r = (r < 0) ? 0 : (r > H_IN - 1 ? H_IN - 1 : r);
        srow[i] = r;
    }
    __syncthreads();

    const int wq = blockIdx.x * 128 + t;
    if (wq >= WQ) return;

    const float4* xin = (const float4*)x + (size_t)bc * H_IN * WQ + wq;

    if (TAPS > 0) {
        float4 a0 = make_float4(0,0,0,0), a1 = a0, a2 = a0, a3 = a0, a4 = a0;
#pragma unroll
        for (int p = 0; p < TAPS; ++p) {
            float4 v;
            float  w;
            v = __ldg(xin + (size_t)srow[0 * TAPS + p] * WQ); w = sw[0 * TAPS + p];
            a0.x += w * v.x; a0.y += w * v.y; a0.z += w * v.z; a0.w += w * v.w;
            v = __ldg(xin + (size_t)srow[1 * TAPS + p] * WQ); w = sw[1 * TAPS + p];
            a1.x += w * v.x; a1.y += w * v.y; a1.z += w * v.z; a1.w += w * v.w;
            v = __ldg(xin + (size_t)srow[2 * TAPS + p] * WQ); w = sw[2 * TAPS + p];
            a2.x += w * v.x; a2.y += w * v.y; a2.z += w * v.z; a2.w += w * v.w;
            v = __ldg(xin + (size_t)srow[3 * TAPS + p] * WQ); w = sw[3 * TAPS + p];
            a3.x += w * v.x; a3.y += w * v.y; a3.z += w * v.z; a3.w += w * v.w;
            v = __ldg(xin + (size_t)srow[4 * TAPS + p] * WQ); w = sw[4 * TAPS + p];
            a4.x += w * v.x; a4.y += w * v.y; a4.z += w * v.z; a4.w += w * v.w;
        }
        float4* mid4 = (float4*)g_mid + ((size_t)bc * OH + oh0) * WQ + wq;
        mid4[0 * WQ] = a0;
        mid4[1 * WQ] = a1;
        mid4[2 * WQ] = a2;
        mid4[3 * WQ] = a3;
        mid4[4 * WQ] = a4;
    } else {
        for (int g = 0; g < G_OH; ++g) {
            float4 acc = make_float4(0,0,0,0);
            for (int p = 0; p < taps; ++p) {
                const float  w = sw[g * taps + p];
                const float4 v = __ldg(xin + (size_t)srow[g * taps + p] * WQ);
                acc.x += w * v.x; acc.y += w * v.y; acc.z += w * v.z; acc.w += w * v.w;
            }
            ((float4*)g_mid)[((size_t)bc * OH + oh0 + g) * WQ + wq] = acc;
        }
    }
}

// ---------------------------------------------------------------------------
// Pass 2: horizontal resample. Contiguous taps -> 5 aligned LDS.128 per
// output, accumulated per-float4 as each load lands (no staging array ->
// low reg pressure). __launch_bounds__(480,2) guarantees 2 blocks/SM so the
// double-buffered pipeline keeps its latency hiding.
// grid: (1, OH/R, BC), block: 480
// ---------------------------------------------------------------------------
#define R_ROWS2 9                        // 270 % 9 == 0
#define SROW_PAD4 488                    // float4 slots; base4+4 <= 483 < 488

// Dot of 16 contiguous weights against window starting at element OFF within
// the 5-float4 aligned span. All positions compile-time; one q live at a time.
template <int OFF>
__device__ __forceinline__ float dot20(const float4* __restrict__ cur4,
                                       int base4,
                                       const float* __restrict__ w)
{
    float a0 = 0.f, a1 = 0.f;
#pragma unroll
    for (int j = 0; j < 5; ++j) {
        if (OFF == 0 && j == 4) break;   // last float4 unused when aligned
        const float4 q = cur4[base4 + j];
        const float e[4] = {q.x, q.y, q.z, q.w};
#pragma unroll
        for (int k = 0; k < 4; ++k) {
            const int p = 4 * j + k - OFF;
            if (p >= 0 && p < 16) {
                if ((p & 1) == 0) a0 += w[p] * e[k];
                else              a1 += w[p] * e[k];
            }
        }
    }
    return a0 + a1;
}

template <int TAPS>
__global__ void __launch_bounds__(480, 2)
pass2_horiz(const float* __restrict__ w_w,
            const int* __restrict__ idx_w,
            float* __restrict__ out,
            int taps_rt)
{
    const int taps = (TAPS > 0) ? TAPS : taps_rt;
    __shared__ float4 buf4[2][SROW_PAD4];

    const int t   = threadIdx.x;         // == ow (OW == 480)
    const int bc  = blockIdx.z;
    const int oh0 = blockIdx.y * R_ROWS2;

    // Registerized per-thread weights + clamped indices
    float wreg[(TAPS > 0) ? TAPS : MAX_TAPS];
    int   creg[(TAPS > 0) ? TAPS : MAX_TAPS];
#pragma unroll
    for (int p = 0; p < ((TAPS > 0) ? TAPS : MAX_TAPS); ++p) {
        if (TAPS == 0 && p >= taps) break;
        wreg[p] = w_w[t * taps + p];
        int c = idx_w[t * taps + p];
        c = (c < 0) ? 0 : (c > W_IN - 1 ? W_IN - 1 : c);
        creg[p] = c;
    }

    // Contiguity check (interior outputs: taps are consecutive columns)
    bool contig = true;
#pragma unroll
    for (int p = 1; p < ((TAPS > 0) ? TAPS : MAX_TAPS); ++p) {
        if (TAPS == 0 && p >= taps) break;
        contig = contig && (creg[p] == creg[0] + p);
    }
    const int start = creg[0];
    const int off   = start & 3;
    const int base4 = (start - off) >> 2;

    const float4* rows = (const float4*)g_mid + ((size_t)bc * OH + oh0) * WQ + t;

    float4 v = __ldg(rows);                         // prefetch row 0

#pragma unroll
    for (int r = 0; r < R_ROWS2; ++r) {
        float4* cur4 = buf4[r & 1];

        cur4[t] = v;                                // STS.128, conflict-free
        __syncthreads();

        if (r + 1 < R_ROWS2)
            v = __ldg(rows + (size_t)(r + 1) * WQ); // prefetch next row

        float o;
        if (contig && TAPS == 16) {
            switch (off) {
            case 0:  o = dot20<0>(cur4, base4, wreg); break;
            case 1:  o = dot20<1>(cur4, base4, wreg); break;
            case 2:  o = dot20<2>(cur4, base4, wreg); break;
            default: o = dot20<3>(cur4, base4, wreg); break;
            }
        } else {
            // scalar fallback (edge mirror threads / generic taps)
            const float* cur = (const float*)cur4;
            float a0 = 0.f, a1 = 0.f;
#pragma unroll
            for (int p = 0; p < ((TAPS > 0) ? TAPS : MAX_TAPS); p += 2) {
                if (TAPS == 0 && p >= taps) break;
                a0 += wreg[p] * cur[creg[p]];
                if (TAPS > 0 || p + 1 < taps)
                    a1 += wreg[p + 1] * cur[creg[p + 1]];
            }
            o = a0 + a1;
        }

        out[((size_t)bc * OH + oh0 + r) * OW + t] = o;
    }
}

// ---------------------------------------------------------------------------
// kernel_launch
// inputs: x(f32), w_h(f32), idx_h(i32), w_w(f32), idx_w(i32); output f32
// ---------------------------------------------------------------------------
extern "C" void kernel_launch(void* const* d_in, const int* in_sizes, int n_in,
                              void* d_out, int out_size)
{
    const float* x     = (const float*)d_in[0];
    const float* w_h   = (const float*)d_in[1];
    const int*   idx_h = (const int*)d_in[2];
    const float* w_w   = (const float*)d_in[3];
    const int*   idx_w = (const int*)d_in[4];
    float*       out   = (float*)d_out;

    int taps_h = in_sizes[1] / OH;
    int taps_w = in_sizes[3] / OW;
    if (taps_h > MAX_TAPS) taps_h = MAX_TAPS;
    if (taps_w > MAX_TAPS) taps_w = MAX_TAPS;

    {
        dim3 grid((WQ + 127) / 128, OH / G_OH, BC);  // (4, 54, 24)
        if (taps_h == 16)
            pass1_vert<16><<<grid, 128>>>(x, w_h, idx_h, taps_h);
        else
            pass1_vert<0><<<grid, 128>>>(x, w_h, idx_h, taps_h);
    }
    {
        dim3 grid(1, OH / R_ROWS2, BC);              // (1, 30, 24)
        if (taps_w == 16)
            pass2_horiz<16><<<grid, 480>>>(w_w, idx_w, out, taps_w);
        else
            pass2_horiz<0><<<grid, 480>>>(w_w, idx_w, out, taps_w);
    }
}